// round 1
// baseline (speedup 1.0000x reference)
#include <cuda_runtime.h>
#include <cuda_bf16.h>
#include <math.h>

#define D_MODEL 1024
#define D_MID   4096
#define NHEAD   16
#define HDIM    64
#define SEQ     2048
#define BATCH   2
#define NROWS   (BATCH * SEQ)      // 4096
#define LN_EPS  1e-5f

// -------------------- scratch (device globals, no allocation) --------------------
__device__ float g_nx [NROWS * D_MODEL];        // 16 MB  (LN output, reused)
__device__ float g_qkv[NROWS * 3 * D_MODEL];    // 48 MB
__device__ float g_ctx[NROWS * D_MODEL];        // 16 MB
__device__ float g_x1 [NROWS * D_MODEL];        // 16 MB  (x + attn residual)
__device__ float g_h  [NROWS * D_MID];          // 64 MB  (FFN mid)

// -------------------- LayerNorm --------------------
__global__ void __launch_bounds__(256) ln_kernel(
    const float* __restrict__ x, const float* __restrict__ g,
    const float* __restrict__ be, float* __restrict__ out)
{
    int row = blockIdx.x;
    int tid = threadIdx.x;
    const float4* xr = reinterpret_cast<const float4*>(x + (size_t)row * D_MODEL);
    float4 v = xr[tid];
    float s  = v.x + v.y + v.z + v.w;
    float ss = v.x*v.x + v.y*v.y + v.z*v.z + v.w*v.w;

    __shared__ float shs[8], shss[8];
    #pragma unroll
    for (int o = 16; o > 0; o >>= 1) {
        s  += __shfl_down_sync(0xffffffffu, s,  o);
        ss += __shfl_down_sync(0xffffffffu, ss, o);
    }
    int w = tid >> 5, lane = tid & 31;
    if (lane == 0) { shs[w] = s; shss[w] = ss; }
    __syncthreads();
    if (w == 0) {
        s  = (lane < 8) ? shs[lane]  : 0.f;
        ss = (lane < 8) ? shss[lane] : 0.f;
        #pragma unroll
        for (int o = 4; o > 0; o >>= 1) {
            s  += __shfl_down_sync(0xffffffffu, s,  o);
            ss += __shfl_down_sync(0xffffffffu, ss, o);
        }
        if (lane == 0) { shs[0] = s; shss[0] = ss; }
    }
    __syncthreads();
    float mu  = shs[0] * (1.f / D_MODEL);
    float var = shss[0] * (1.f / D_MODEL) - mu * mu;
    float rstd = rsqrtf(var + LN_EPS);

    float4 gv = reinterpret_cast<const float4*>(g)[tid];
    float4 bv = reinterpret_cast<const float4*>(be)[tid];
    float4 o4;
    o4.x = (v.x - mu) * rstd * gv.x + bv.x;
    o4.y = (v.y - mu) * rstd * gv.y + bv.y;
    o4.z = (v.z - mu) * rstd * gv.z + bv.z;
    o4.w = (v.w - mu) * rstd * gv.w + bv.w;
    reinterpret_cast<float4*>(out + (size_t)row * D_MODEL)[tid] = o4;
}

// -------------------- GELU --------------------
__device__ __forceinline__ float gelu_f(float x) {
    float x3 = x * x * x;
    return 0.5f * x * (1.f + tanhf(0.7978845608028654f * (x + 0.044715f * x3)));
}

// -------------------- SGEMM: C = A[M,K] @ B[K,N] + bias (+epilogue) --------------------
// EPI: 0 = bias only, 1 = bias + GELU, 2 = bias + residual
template<int EPI>
__global__ void __launch_bounds__(256) sgemm_k(
    const float* __restrict__ A, const float* __restrict__ B,
    const float* __restrict__ bias, const float* __restrict__ res,
    float* __restrict__ C, int M, int N, int K)
{
    __shared__ float As[8][128];
    __shared__ float Bs[8][128];

    int bm = blockIdx.y * 128;
    int bn = blockIdx.x * 128;
    int tid = threadIdx.x;
    int tx = tid & 15;        // col group (8 cols)
    int ty = tid >> 4;        // row group (8 rows)

    // A tile load: 128 rows x 8 k, one float4 per thread (2 threads / row)
    int arow = tid >> 1;
    int acol = (tid & 1) * 4;
    // B tile load: 8 k x 128 cols, one float4 per thread
    int brow = tid >> 5;
    int bcol = (tid & 31) * 4;

    const float* Aptr = A + (size_t)(bm + arow) * K + acol;
    const float* Bptr = B + (size_t)brow * N + bn + bcol;

    float acc[8][8];
    #pragma unroll
    for (int i = 0; i < 8; ++i)
        #pragma unroll
        for (int j = 0; j < 8; ++j) acc[i][j] = 0.f;

    for (int k0 = 0; k0 < K; k0 += 8) {
        float4 av = *reinterpret_cast<const float4*>(Aptr + k0);
        float4 bv = *reinterpret_cast<const float4*>(Bptr + (size_t)k0 * N);
        __syncthreads();
        As[acol + 0][arow] = av.x;
        As[acol + 1][arow] = av.y;
        As[acol + 2][arow] = av.z;
        As[acol + 3][arow] = av.w;
        *reinterpret_cast<float4*>(&Bs[brow][bcol]) = bv;
        __syncthreads();

        #pragma unroll
        for (int kk = 0; kk < 8; ++kk) {
            float a[8], b[8];
            *reinterpret_cast<float4*>(a)     = *reinterpret_cast<float4*>(&As[kk][ty * 8]);
            *reinterpret_cast<float4*>(a + 4) = *reinterpret_cast<float4*>(&As[kk][ty * 8 + 4]);
            *reinterpret_cast<float4*>(b)     = *reinterpret_cast<float4*>(&Bs[kk][tx * 8]);
            *reinterpret_cast<float4*>(b + 4) = *reinterpret_cast<float4*>(&Bs[kk][tx * 8 + 4]);
            #pragma unroll
            for (int i = 0; i < 8; ++i)
                #pragma unroll
                for (int j = 0; j < 8; ++j)
                    acc[i][j] = fmaf(a[i], b[j], acc[i][j]);
        }
    }

    // epilogue
    #pragma unroll
    for (int i = 0; i < 8; ++i) {
        int m = bm + ty * 8 + i;
        #pragma unroll
        for (int j = 0; j < 8; ++j) {
            int n = bn + tx * 8 + j;
            float c = acc[i][j] + bias[n];
            if (EPI == 1) c = gelu_f(c);
            if (EPI == 2) c += res[(size_t)m * N + n];
            C[(size_t)m * N + n] = c;
        }
    }
}

// -------------------- Flash attention (causal, fp32) --------------------
// grid: (qtiles=32, H=16, B=2), block 256, dynamic smem ~72KB
__global__ void __launch_bounds__(256) flash_attn_k(
    const float* __restrict__ qkv, float* __restrict__ ctx)
{
    extern __shared__ float sm[];
    const int PAD = 68;
    float* Qs   = sm;                   // 64 x 68
    float* Ks   = Qs + 64 * PAD;        // 64 x 68
    float* Vs   = Ks + 64 * PAD;        // 64 x 68
    float* Ss   = Vs + 64 * PAD;        // 64 x 68
    float* mrow = Ss + 64 * PAD;        // 64
    float* lrow = mrow + 64;            // 64
    float* cf   = lrow + 64;            // 64
    float* red  = cf + 64;              // 256

    const int qt = blockIdx.x;
    const int h  = blockIdx.y;
    const int b  = blockIdx.z;
    const int tid = threadIdx.x;
    const float scale = 0.03125f;       // 1/sqrt(1024)

    const size_t base = (size_t)b * SEQ * (3 * D_MODEL);
    const float* qp = qkv + base + h * HDIM;
    const float* kp = qkv + base + D_MODEL + h * HDIM;
    const float* vp = qkv + base + 2 * D_MODEL + h * HDIM;
    const int qbase = qt * 64;

    // load Q tile (scaled)
    for (int i = tid; i < 64 * 16; i += 256) {
        int r = i >> 4, c4 = (i & 15) * 4;
        float4 v = *reinterpret_cast<const float4*>(qp + (size_t)(qbase + r) * (3 * D_MODEL) + c4);
        Qs[r * PAD + c4 + 0] = v.x * scale;
        Qs[r * PAD + c4 + 1] = v.y * scale;
        Qs[r * PAD + c4 + 2] = v.z * scale;
        Qs[r * PAD + c4 + 3] = v.w * scale;
    }
    if (tid < 64) { mrow[tid] = -INFINITY; lrow[tid] = 0.f; }

    const int ty = tid >> 4, tx = tid & 15;
    const int r0 = ty * 4,  c0 = tx * 4;
    float acc[4][4];
    #pragma unroll
    for (int i = 0; i < 4; ++i)
        #pragma unroll
        for (int j = 0; j < 4; ++j) acc[i][j] = 0.f;

    __syncthreads();

    for (int jt = 0; jt <= qt; ++jt) {
        const int jbase = jt * 64;
        // load K,V tiles
        for (int i = tid; i < 64 * 16; i += 256) {
            int r = i >> 4, c4 = (i & 15) * 4;
            float4 kv = *reinterpret_cast<const float4*>(kp + (size_t)(jbase + r) * (3 * D_MODEL) + c4);
            float4 vv = *reinterpret_cast<const float4*>(vp + (size_t)(jbase + r) * (3 * D_MODEL) + c4);
            *reinterpret_cast<float4*>(&Ks[r * PAD + c4]) = kv;
            *reinterpret_cast<float4*>(&Vs[r * PAD + c4]) = vv;
        }
        __syncthreads();

        // S = Q K^T (4x4 per thread)
        float s[4][4];
        #pragma unroll
        for (int i = 0; i < 4; ++i)
            #pragma unroll
            for (int j = 0; j < 4; ++j) s[i][j] = 0.f;
        for (int kk = 0; kk < 64; ++kk) {
            float qa[4], kb[4];
            #pragma unroll
            for (int i = 0; i < 4; ++i) qa[i] = Qs[(r0 + i) * PAD + kk];
            #pragma unroll
            for (int j = 0; j < 4; ++j) kb[j] = Ks[(c0 + j) * PAD + kk];
            #pragma unroll
            for (int i = 0; i < 4; ++i)
                #pragma unroll
                for (int j = 0; j < 4; ++j)
                    s[i][j] = fmaf(qa[i], kb[j], s[i][j]);
        }
        if (jt == qt) {  // causal mask within diagonal tile
            #pragma unroll
            for (int i = 0; i < 4; ++i)
                #pragma unroll
                for (int j = 0; j < 4; ++j)
                    if (r0 + i < c0 + j) s[i][j] = -1e30f;
        }
        #pragma unroll
        for (int i = 0; i < 4; ++i)
            #pragma unroll
            for (int j = 0; j < 4; ++j)
                Ss[(r0 + i) * PAD + c0 + j] = s[i][j];
        __syncthreads();

        // online softmax: 4 threads per row
        {
            int row = tid >> 2, seg = tid & 3;
            float* srow = Ss + row * PAD + seg * 16;
            float lm = -INFINITY;
            #pragma unroll
            for (int j = 0; j < 16; ++j) lm = fmaxf(lm, srow[j]);
            red[row * 4 + seg] = lm;
            __syncthreads();
            if (seg == 0) {
                float mn = fmaxf(fmaxf(red[row * 4], red[row * 4 + 1]),
                                 fmaxf(red[row * 4 + 2], red[row * 4 + 3]));
                mn = fmaxf(mn, mrow[row]);
                cf[row] = __expf(mrow[row] - mn);
                mrow[row] = mn;
            }
            __syncthreads();
            float mr = mrow[row];
            float lsum = 0.f;
            #pragma unroll
            for (int j = 0; j < 16; ++j) {
                float e = __expf(srow[j] - mr);
                srow[j] = e;
                lsum += e;
            }
            red[row * 4 + seg] = lsum;
            __syncthreads();
            if (seg == 0) {
                lrow[row] = lrow[row] * cf[row] +
                            red[row * 4] + red[row * 4 + 1] +
                            red[row * 4 + 2] + red[row * 4 + 3];
            }
            __syncthreads();
        }

        // O = O*cf + P @ V
        #pragma unroll
        for (int i = 0; i < 4; ++i) {
            float f = cf[r0 + i];
            #pragma unroll
            for (int j = 0; j < 4; ++j) acc[i][j] *= f;
        }
        for (int kk = 0; kk < 64; ++kk) {
            float p[4], vv[4];
            #pragma unroll
            for (int i = 0; i < 4; ++i) p[i] = Ss[(r0 + i) * PAD + kk];
            #pragma unroll
            for (int j = 0; j < 4; ++j) vv[j] = Vs[kk * PAD + c0 + j];
            #pragma unroll
            for (int i = 0; i < 4; ++i)
                #pragma unroll
                for (int j = 0; j < 4; ++j)
                    acc[i][j] = fmaf(p[i], vv[j], acc[i][j]);
        }
        __syncthreads();
    }

    // write ctx [B, L, D]
    #pragma unroll
    for (int i = 0; i < 4; ++i) {
        float inv = 1.f / lrow[r0 + i];
        size_t orow = ((size_t)b * SEQ + qbase + r0 + i) * D_MODEL + h * HDIM + c0;
        #pragma unroll
        for (int j = 0; j < 4; ++j)
            ctx[orow + j] = acc[i][j] * inv;
    }
}

// -------------------- launch --------------------
extern "C" void kernel_launch(void* const* d_in, const int* in_sizes, int n_in,
                              void* d_out, int out_size)
{
    const float* x     = (const float*)d_in[0];
    const float* w_qkv = (const float*)d_in[1];
    const float* b_qkv = (const float*)d_in[2];
    const float* w_o   = (const float*)d_in[3];
    const float* b_o   = (const float*)d_in[4];
    const float* g1    = (const float*)d_in[5];
    const float* be1   = (const float*)d_in[6];
    const float* g2    = (const float*)d_in[7];
    const float* be2   = (const float*)d_in[8];
    const float* w1    = (const float*)d_in[9];
    const float* b1    = (const float*)d_in[10];
    const float* w2    = (const float*)d_in[11];
    const float* b2    = (const float*)d_in[12];
    float* out = (float*)d_out;

    float *p_nx, *p_qkv, *p_ctx, *p_x1, *p_h;
    cudaGetSymbolAddress((void**)&p_nx,  g_nx);
    cudaGetSymbolAddress((void**)&p_qkv, g_qkv);
    cudaGetSymbolAddress((void**)&p_ctx, g_ctx);
    cudaGetSymbolAddress((void**)&p_x1,  g_x1);
    cudaGetSymbolAddress((void**)&p_h,   g_h);

    static const int FLASH_SMEM = (4 * 64 * 68 + 64 * 3 + 256) * (int)sizeof(float);
    cudaFuncSetAttribute(flash_attn_k, cudaFuncAttributeMaxDynamicSharedMemorySize, FLASH_SMEM);

    // 1) nx = LN1(x)
    ln_kernel<<<NROWS, 256>>>(x, g1, be1, p_nx);

    // 2) qkv = nx @ w_qkv + b_qkv     [4096, 3072]
    sgemm_k<0><<<dim3(3 * D_MODEL / 128, NROWS / 128), 256>>>(
        p_nx, w_qkv, b_qkv, nullptr, p_qkv, NROWS, 3 * D_MODEL, D_MODEL);

    // 3) ctx = causal attention(q,k,v)
    flash_attn_k<<<dim3(SEQ / 64, NHEAD, BATCH), 256, FLASH_SMEM>>>(p_qkv, p_ctx);

    // 4) x1 = x + ctx @ w_o + b_o
    sgemm_k<2><<<dim3(D_MODEL / 128, NROWS / 128), 256>>>(
        p_ctx, w_o, b_o, x, p_x1, NROWS, D_MODEL, D_MODEL);

    // 5) nx = LN2(x1)
    ln_kernel<<<NROWS, 256>>>(p_x1, g2, be2, p_nx);

    // 6) h = gelu(nx @ w1 + b1)       [4096, 4096]
    sgemm_k<1><<<dim3(D_MID / 128, NROWS / 128), 256>>>(
        p_nx, w1, b1, nullptr, p_h, NROWS, D_MID, D_MODEL);

    // 7) out = x1 + h @ w2 + b2       [4096, 1024]
    sgemm_k<2><<<dim3(D_MODEL / 128, NROWS / 128), 256>>>(
        p_h, w2, b2, p_x1, out, NROWS, D_MODEL, D_MID);
}

// round 4
// speedup vs baseline: 1.8226x; 1.8226x over previous
#include <cuda_runtime.h>
#include <cuda_bf16.h>
#include <math.h>
#include <stdint.h>

#define D_MODEL 1024
#define D_MID   4096
#define NHEAD   16
#define HDIM    64
#define SEQ     2048
#define BATCH   2
#define NROWS   (BATCH * SEQ)      // 4096
#define LN_EPS  1e-5f

// -------------------- scratch (device globals, no allocation) --------------------
__device__ float g_nx [NROWS * D_MODEL];
__device__ float g_qkv[NROWS * 3 * D_MODEL];
__device__ float g_ctx[NROWS * D_MODEL];
__device__ float g_x1 [NROWS * D_MODEL];
__device__ float g_h  [NROWS * D_MID];

// -------------------- LayerNorm --------------------
__global__ void __launch_bounds__(256) ln_kernel(
    const float* __restrict__ x, const float* __restrict__ g,
    const float* __restrict__ be, float* __restrict__ out)
{
    int row = blockIdx.x;
    int tid = threadIdx.x;
    const float4* xr = reinterpret_cast<const float4*>(x + (size_t)row * D_MODEL);
    float4 v = xr[tid];
    float s  = v.x + v.y + v.z + v.w;
    float ss = v.x*v.x + v.y*v.y + v.z*v.z + v.w*v.w;

    __shared__ float shs[8], shss[8];
    #pragma unroll
    for (int o = 16; o > 0; o >>= 1) {
        s  += __shfl_down_sync(0xffffffffu, s,  o);
        ss += __shfl_down_sync(0xffffffffu, ss, o);
    }
    int w = tid >> 5, lane = tid & 31;
    if (lane == 0) { shs[w] = s; shss[w] = ss; }
    __syncthreads();
    if (w == 0) {
        s  = (lane < 8) ? shs[lane]  : 0.f;
        ss = (lane < 8) ? shss[lane] : 0.f;
        #pragma unroll
        for (int o = 4; o > 0; o >>= 1) {
            s  += __shfl_down_sync(0xffffffffu, s,  o);
            ss += __shfl_down_sync(0xffffffffu, ss, o);
        }
        if (lane == 0) { shs[0] = s; shss[0] = ss; }
    }
    __syncthreads();
    float mu  = shs[0] * (1.f / D_MODEL);
    float var = shss[0] * (1.f / D_MODEL) - mu * mu;
    float rstd = rsqrtf(var + LN_EPS);

    float4 gv = reinterpret_cast<const float4*>(g)[tid];
    float4 bv = reinterpret_cast<const float4*>(be)[tid];
    float4 o4;
    o4.x = (v.x - mu) * rstd * gv.x + bv.x;
    o4.y = (v.y - mu) * rstd * gv.y + bv.y;
    o4.z = (v.z - mu) * rstd * gv.z + bv.z;
    o4.w = (v.w - mu) * rstd * gv.w + bv.w;
    reinterpret_cast<float4*>(out + (size_t)row * D_MODEL)[tid] = o4;
}

// -------------------- GELU --------------------
__device__ __forceinline__ float gelu_f(float x) {
    float x3 = x * x * x;
    return 0.5f * x * (1.f + tanhf(0.7978845608028654f * (x + 0.044715f * x3)));
}

// -------------------- tf32 helpers --------------------
__device__ __forceinline__ float f2tf32(float f) {
    uint32_t r;
    asm("cvt.rna.tf32.f32 %0, %1;" : "=r"(r) : "f"(f));
    return __uint_as_float(r);
}

__device__ __forceinline__ void mma_tf32(
    float c[4], const uint32_t a[4], const uint32_t b[2])
{
    asm volatile(
        "mma.sync.aligned.m16n8k8.row.col.f32.tf32.tf32.f32 "
        "{%0,%1,%2,%3}, {%4,%5,%6,%7}, {%8,%9}, {%0,%1,%2,%3};"
        : "+f"(c[0]), "+f"(c[1]), "+f"(c[2]), "+f"(c[3])
        : "r"(a[0]), "r"(a[1]), "r"(a[2]), "r"(a[3]),
          "r"(b[0]), "r"(b[1]));
}

// -------------------- TF32 tensor-core GEMM --------------------
// C[M,N] = A[M,K] @ B[K,N] + bias (+epilogue)
// 128x128 block tile, K-tile 32, 8 warps each 32(m) x 64(n).
// EPI: 0 = bias, 1 = bias+GELU, 2 = bias+residual
#define LDA 36     // A smem row pitch (128 rows x 36)
#define LDB 136    // B smem row pitch (32 rows x 136)

template<int EPI>
__global__ void __launch_bounds__(256) tgemm_k(
    const float* __restrict__ A, const float* __restrict__ B,
    const float* __restrict__ bias, const float* __restrict__ res,
    float* __restrict__ C, int M, int N, int K)
{
    __shared__ float As[128 * LDA];   // 18 KB
    __shared__ float Bs[32 * LDB];    // 17 KB

    const int bm = blockIdx.y * 128;
    const int bn = blockIdx.x * 128;
    const int tid  = threadIdx.x;
    const int wid  = tid >> 5;
    const int lane = tid & 31;
    const int gq = lane >> 2;      // groupID (0..7)
    const int tg = lane & 3;       // thread-in-group

    const int m0 = (wid & 3) * 32;     // warp m offset in tile
    const int n0 = (wid >> 2) * 64;    // warp n offset in tile

    float4 aTmp[4], bTmp[4];

    float acc[2][8][4];
    #pragma unroll
    for (int i = 0; i < 2; ++i)
        #pragma unroll
        for (int j = 0; j < 8; ++j)
            #pragma unroll
            for (int t = 0; t < 4; ++t) acc[i][j][t] = 0.f;

    const int nkt = K >> 5;

    // prefetch tile 0
    #pragma unroll
    for (int l = 0; l < 4; ++l) {
        int v = tid + l * 256;
        aTmp[l] = *reinterpret_cast<const float4*>(A + (size_t)(bm + (v >> 3)) * K + ((v & 7) << 2));
        bTmp[l] = *reinterpret_cast<const float4*>(B + (size_t)(v >> 5) * N + bn + ((v & 31) << 2));
    }

    for (int kt = 0; kt < nkt; ++kt) {
        __syncthreads();
        // store staged tile to smem with tf32 rounding
        #pragma unroll
        for (int l = 0; l < 4; ++l) {
            int v = tid + l * 256;
            float* ap = &As[(v >> 3) * LDA + ((v & 7) << 2)];
            ap[0] = f2tf32(aTmp[l].x); ap[1] = f2tf32(aTmp[l].y);
            ap[2] = f2tf32(aTmp[l].z); ap[3] = f2tf32(aTmp[l].w);
            float* bp = &Bs[(v >> 5) * LDB + ((v & 31) << 2)];
            bp[0] = f2tf32(bTmp[l].x); bp[1] = f2tf32(bTmp[l].y);
            bp[2] = f2tf32(bTmp[l].z); bp[3] = f2tf32(bTmp[l].w);
        }
        __syncthreads();

        // prefetch next tile
        if (kt + 1 < nkt) {
            const int koff = (kt + 1) << 5;
            #pragma unroll
            for (int l = 0; l < 4; ++l) {
                int v = tid + l * 256;
                aTmp[l] = *reinterpret_cast<const float4*>(A + (size_t)(bm + (v >> 3)) * K + koff + ((v & 7) << 2));
                bTmp[l] = *reinterpret_cast<const float4*>(B + (size_t)(koff + (v >> 5)) * N + bn + ((v & 31) << 2));
            }
        }

        // compute: 4 k-steps of 8
        #pragma unroll
        for (int kk = 0; kk < 4; ++kk) {
            const int k = kk << 3;
            uint32_t afr[2][4], bfr[8][2];
            #pragma unroll
            for (int i = 0; i < 2; ++i) {
                int r = m0 + i * 16 + gq;
                int c = k + tg;
                // PTX m16n8k8 tf32 A layout:
                // a0=A[g][t] a1=A[g+8][t] a2=A[g][t+4] a3=A[g+8][t+4]
                afr[i][0] = __float_as_uint(As[r * LDA + c]);
                afr[i][1] = __float_as_uint(As[(r + 8) * LDA + c]);
                afr[i][2] = __float_as_uint(As[r * LDA + c + 4]);
                afr[i][3] = __float_as_uint(As[(r + 8) * LDA + c + 4]);
            }
            #pragma unroll
            for (int j = 0; j < 8; ++j) {
                int col = n0 + j * 8 + gq;
                int row = k + tg;
                bfr[j][0] = __float_as_uint(Bs[row * LDB + col]);
                bfr[j][1] = __float_as_uint(Bs[(row + 4) * LDB + col]);
            }
            #pragma unroll
            for (int i = 0; i < 2; ++i)
                #pragma unroll
                for (int j = 0; j < 8; ++j)
                    mma_tf32(acc[i][j], afr[i], bfr[j]);
        }
    }

    // epilogue: c0,c1 at (row, 2*tg), c2,c3 at (row+8, 2*tg)
    #pragma unroll
    for (int i = 0; i < 2; ++i) {
        #pragma unroll
        for (int half = 0; half < 2; ++half) {
            int m = bm + m0 + i * 16 + gq + half * 8;
            #pragma unroll
            for (int j = 0; j < 8; ++j) {
                int n = bn + n0 + j * 8 + 2 * tg;
                float c0 = acc[i][j][half * 2 + 0] + bias[n];
                float c1 = acc[i][j][half * 2 + 1] + bias[n + 1];
                if (EPI == 1) { c0 = gelu_f(c0); c1 = gelu_f(c1); }
                if (EPI == 2) {
                    const float2 r2 = *reinterpret_cast<const float2*>(res + (size_t)m * N + n);
                    c0 += r2.x; c1 += r2.y;
                }
                float2 o2; o2.x = c0; o2.y = c1;
                *reinterpret_cast<float2*>(C + (size_t)m * N + n) = o2;
            }
        }
    }
}

// -------------------- Flash attention (causal, fp32) --------------------
__global__ void __launch_bounds__(256) flash_attn_k(
    const float* __restrict__ qkv, float* __restrict__ ctx)
{
    extern __shared__ float sm[];
    const int PAD = 68;
    float* Qs   = sm;
    float* Ks   = Qs + 64 * PAD;
    float* Vs   = Ks + 64 * PAD;
    float* Ss   = Vs + 64 * PAD;
    float* mrow = Ss + 64 * PAD;
    float* lrow = mrow + 64;
    float* cf   = lrow + 64;
    float* red  = cf + 64;

    const int qt = blockIdx.x;
    const int h  = blockIdx.y;
    const int b  = blockIdx.z;
    const int tid = threadIdx.x;
    const float scale = 0.03125f;

    const size_t base = (size_t)b * SEQ * (3 * D_MODEL);
    const float* qp = qkv + base + h * HDIM;
    const float* kp = qkv + base + D_MODEL + h * HDIM;
    const float* vp = qkv + base + 2 * D_MODEL + h * HDIM;
    const int qbase = qt * 64;

    for (int i = tid; i < 64 * 16; i += 256) {
        int r = i >> 4, c4 = (i & 15) * 4;
        float4 v = *reinterpret_cast<const float4*>(qp + (size_t)(qbase + r) * (3 * D_MODEL) + c4);
        Qs[r * PAD + c4 + 0] = v.x * scale;
        Qs[r * PAD + c4 + 1] = v.y * scale;
        Qs[r * PAD + c4 + 2] = v.z * scale;
        Qs[r * PAD + c4 + 3] = v.w * scale;
    }
    if (tid < 64) { mrow[tid] = -INFINITY; lrow[tid] = 0.f; }

    const int ty = tid >> 4, tx = tid & 15;
    const int r0 = ty * 4,  c0 = tx * 4;
    float acc[4][4];
    #pragma unroll
    for (int i = 0; i < 4; ++i)
        #pragma unroll
        for (int j = 0; j < 4; ++j) acc[i][j] = 0.f;

    __syncthreads();

    for (int jt = 0; jt <= qt; ++jt) {
        const int jbase = jt * 64;
        for (int i = tid; i < 64 * 16; i += 256) {
            int r = i >> 4, c4 = (i & 15) * 4;
            float4 kv = *reinterpret_cast<const float4*>(kp + (size_t)(jbase + r) * (3 * D_MODEL) + c4);
            float4 vv = *reinterpret_cast<const float4*>(vp + (size_t)(jbase + r) * (3 * D_MODEL) + c4);
            *reinterpret_cast<float4*>(&Ks[r * PAD + c4]) = kv;
            *reinterpret_cast<float4*>(&Vs[r * PAD + c4]) = vv;
        }
        __syncthreads();

        float s[4][4];
        #pragma unroll
        for (int i = 0; i < 4; ++i)
            #pragma unroll
            for (int j = 0; j < 4; ++j) s[i][j] = 0.f;
        for (int kk = 0; kk < 64; ++kk) {
            float qa[4], kb[4];
            #pragma unroll
            for (int i = 0; i < 4; ++i) qa[i] = Qs[(r0 + i) * PAD + kk];
            #pragma unroll
            for (int j = 0; j < 4; ++j) kb[j] = Ks[(c0 + j) * PAD + kk];
            #pragma unroll
            for (int i = 0; i < 4; ++i)
                #pragma unroll
                for (int j = 0; j < 4; ++j)
                    s[i][j] = fmaf(qa[i], kb[j], s[i][j]);
        }
        if (jt == qt) {
            #pragma unroll
            for (int i = 0; i < 4; ++i)
                #pragma unroll
                for (int j = 0; j < 4; ++j)
                    if (r0 + i < c0 + j) s[i][j] = -1e30f;
        }
        #pragma unroll
        for (int i = 0; i < 4; ++i)
            #pragma unroll
            for (int j = 0; j < 4; ++j)
                Ss[(r0 + i) * PAD + c0 + j] = s[i][j];
        __syncthreads();

        {
            int row = tid >> 2, seg = tid & 3;
            float* srow = Ss + row * PAD + seg * 16;
            float lm = -INFINITY;
            #pragma unroll
            for (int j = 0; j < 16; ++j) lm = fmaxf(lm, srow[j]);
            red[row * 4 + seg] = lm;
            __syncthreads();
            if (seg == 0) {
                float mn = fmaxf(fmaxf(red[row * 4], red[row * 4 + 1]),
                                 fmaxf(red[row * 4 + 2], red[row * 4 + 3]));
                mn = fmaxf(mn, mrow[row]);
                cf[row] = __expf(mrow[row] - mn);
                mrow[row] = mn;
            }
            __syncthreads();
            float mr = mrow[row];
            float lsum = 0.f;
            #pragma unroll
            for (int j = 0; j < 16; ++j) {
                float e = __expf(srow[j] - mr);
                srow[j] = e;
                lsum += e;
            }
            red[row * 4 + seg] = lsum;
            __syncthreads();
            if (seg == 0) {
                lrow[row] = lrow[row] * cf[row] +
                            red[row * 4] + red[row * 4 + 1] +
                            red[row * 4 + 2] + red[row * 4 + 3];
            }
            __syncthreads();
        }

        #pragma unroll
        for (int i = 0; i < 4; ++i) {
            float f = cf[r0 + i];
            #pragma unroll
            for (int j = 0; j < 4; ++j) acc[i][j] *= f;
        }
        for (int kk = 0; kk < 64; ++kk) {
            float p[4], vv[4];
            #pragma unroll
            for (int i = 0; i < 4; ++i) p[i] = Ss[(r0 + i) * PAD + kk];
            #pragma unroll
            for (int j = 0; j < 4; ++j) vv[j] = Vs[kk * PAD + c0 + j];
            #pragma unroll
            for (int i = 0; i < 4; ++i)
                #pragma unroll
                for (int j = 0; j < 4; ++j)
                    acc[i][j] = fmaf(p[i], vv[j], acc[i][j]);
        }
        __syncthreads();
    }

    #pragma unroll
    for (int i = 0; i < 4; ++i) {
        float inv = 1.f / lrow[r0 + i];
        size_t orow = ((size_t)b * SEQ + qbase + r0 + i) * D_MODEL + h * HDIM + c0;
        #pragma unroll
        for (int j = 0; j < 4; ++j)
            ctx[orow + j] = acc[i][j] * inv;
    }
}

// -------------------- launch --------------------
extern "C" void kernel_launch(void* const* d_in, const int* in_sizes, int n_in,
                              void* d_out, int out_size)
{
    const float* x     = (const float*)d_in[0];
    const float* w_qkv = (const float*)d_in[1];
    const float* b_qkv = (const float*)d_in[2];
    const float* w_o   = (const float*)d_in[3];
    const float* b_o   = (const float*)d_in[4];
    const float* g1    = (const float*)d_in[5];
    const float* be1   = (const float*)d_in[6];
    const float* g2    = (const float*)d_in[7];
    const float* be2   = (const float*)d_in[8];
    const float* w1    = (const float*)d_in[9];
    const float* b1    = (const float*)d_in[10];
    const float* w2    = (const float*)d_in[11];
    const float* b2    = (const float*)d_in[12];
    float* out = (float*)d_out;

    float *p_nx, *p_qkv, *p_ctx, *p_x1, *p_h;
    cudaGetSymbolAddress((void**)&p_nx,  g_nx);
    cudaGetSymbolAddress((void**)&p_qkv, g_qkv);
    cudaGetSymbolAddress((void**)&p_ctx, g_ctx);
    cudaGetSymbolAddress((void**)&p_x1,  g_x1);
    cudaGetSymbolAddress((void**)&p_h,   g_h);

    static const int FLASH_SMEM = (4 * 64 * 68 + 64 * 3 + 256) * (int)sizeof(float);
    cudaFuncSetAttribute(flash_attn_k, cudaFuncAttributeMaxDynamicSharedMemorySize, FLASH_SMEM);

    // 1) nx = LN1(x)
    ln_kernel<<<NROWS, 256>>>(x, g1, be1, p_nx);

    // 2) qkv = nx @ w_qkv + b_qkv     [4096, 3072]
    tgemm_k<0><<<dim3(3 * D_MODEL / 128, NROWS / 128), 256>>>(
        p_nx, w_qkv, b_qkv, nullptr, p_qkv, NROWS, 3 * D_MODEL, D_MODEL);

    // 3) ctx = causal attention(q,k,v)
    flash_attn_k<<<dim3(SEQ / 64, NHEAD, BATCH), 256, FLASH_SMEM>>>(p_qkv, p_ctx);

    // 4) x1 = x + ctx @ w_o + b_o
    tgemm_k<2><<<dim3(D_MODEL / 128, NROWS / 128), 256>>>(
        p_ctx, w_o, b_o, x, p_x1, NROWS, D_MODEL, D_MODEL);

    // 5) nx = LN2(x1)
    ln_kernel<<<NROWS, 256>>>(p_x1, g2, be2, p_nx);

    // 6) h = gelu(nx @ w1 + b1)       [4096, 4096]
    tgemm_k<1><<<dim3(D_MID / 128, NROWS / 128), 256>>>(
        p_nx, w1, b1, nullptr, p_h, NROWS, D_MID, D_MODEL);

    // 7) out = x1 + h @ w2 + b2       [4096, 1024]
    tgemm_k<2><<<dim3(D_MODEL / 128, NROWS / 128), 256>>>(
        p_h, w2, b2, p_x1, out, NROWS, D_MODEL, D_MID);
}

// round 5
// speedup vs baseline: 3.0700x; 1.6844x over previous
#include <cuda_runtime.h>
#include <cuda_bf16.h>
#include <math.h>
#include <stdint.h>

#define D_MODEL 1024
#define D_MID   4096
#define NHEAD   16
#define HDIM    64
#define SEQ     2048
#define BATCH   2
#define NROWS   (BATCH * SEQ)      // 4096
#define LN_EPS  1e-5f

// -------------------- scratch (device globals, no allocation) --------------------
__device__ float g_nx [NROWS * D_MODEL];
__device__ float g_qkv[NROWS * 3 * D_MODEL];
__device__ float g_ctx[NROWS * D_MODEL];
__device__ float g_x1 [NROWS * D_MODEL];
__device__ float g_h  [NROWS * D_MID];

// -------------------- LayerNorm --------------------
__global__ void __launch_bounds__(256) ln_kernel(
    const float* __restrict__ x, const float* __restrict__ g,
    const float* __restrict__ be, float* __restrict__ out)
{
    int row = blockIdx.x;
    int tid = threadIdx.x;
    const float4* xr = reinterpret_cast<const float4*>(x + (size_t)row * D_MODEL);
    float4 v = xr[tid];
    float s  = v.x + v.y + v.z + v.w;
    float ss = v.x*v.x + v.y*v.y + v.z*v.z + v.w*v.w;

    __shared__ float shs[8], shss[8];
    #pragma unroll
    for (int o = 16; o > 0; o >>= 1) {
        s  += __shfl_down_sync(0xffffffffu, s,  o);
        ss += __shfl_down_sync(0xffffffffu, ss, o);
    }
    int w = tid >> 5, lane = tid & 31;
    if (lane == 0) { shs[w] = s; shss[w] = ss; }
    __syncthreads();
    if (w == 0) {
        s  = (lane < 8) ? shs[lane]  : 0.f;
        ss = (lane < 8) ? shss[lane] : 0.f;
        #pragma unroll
        for (int o = 4; o > 0; o >>= 1) {
            s  += __shfl_down_sync(0xffffffffu, s,  o);
            ss += __shfl_down_sync(0xffffffffu, ss, o);
        }
        if (lane == 0) { shs[0] = s; shss[0] = ss; }
    }
    __syncthreads();
    float mu  = shs[0] * (1.f / D_MODEL);
    float var = shss[0] * (1.f / D_MODEL) - mu * mu;
    float rstd = rsqrtf(var + LN_EPS);

    float4 gv = reinterpret_cast<const float4*>(g)[tid];
    float4 bv = reinterpret_cast<const float4*>(be)[tid];
    float4 o4;
    o4.x = (v.x - mu) * rstd * gv.x + bv.x;
    o4.y = (v.y - mu) * rstd * gv.y + bv.y;
    o4.z = (v.z - mu) * rstd * gv.z + bv.z;
    o4.w = (v.w - mu) * rstd * gv.w + bv.w;
    reinterpret_cast<float4*>(out + (size_t)row * D_MODEL)[tid] = o4;
}

// -------------------- GELU --------------------
__device__ __forceinline__ float gelu_f(float x) {
    float x3 = x * x * x;
    return 0.5f * x * (1.f + tanhf(0.7978845608028654f * (x + 0.044715f * x3)));
}

// -------------------- tf32 helpers --------------------
__device__ __forceinline__ float f2tf32(float f) {
    uint32_t r;
    asm("cvt.rna.tf32.f32 %0, %1;" : "=r"(r) : "f"(f));
    return __uint_as_float(r);
}

__device__ __forceinline__ void mma_tf32(
    float c[4], const uint32_t a[4], const uint32_t b[2])
{
    asm volatile(
        "mma.sync.aligned.m16n8k8.row.col.f32.tf32.tf32.f32 "
        "{%0,%1,%2,%3}, {%4,%5,%6,%7}, {%8,%9}, {%0,%1,%2,%3};"
        : "+f"(c[0]), "+f"(c[1]), "+f"(c[2]), "+f"(c[3])
        : "r"(a[0]), "r"(a[1]), "r"(a[2]), "r"(a[3]),
          "r"(b[0]), "r"(b[1]));
}

// -------------------- TF32 tensor-core GEMM --------------------
#define LDA 36
#define LDB 136

template<int EPI>
__global__ void __launch_bounds__(256) tgemm_k(
    const float* __restrict__ A, const float* __restrict__ B,
    const float* __restrict__ bias, const float* __restrict__ res,
    float* __restrict__ C, int M, int N, int K)
{
    __shared__ float As[128 * LDA];
    __shared__ float Bs[32 * LDB];

    const int bm = blockIdx.y * 128;
    const int bn = blockIdx.x * 128;
    const int tid  = threadIdx.x;
    const int wid  = tid >> 5;
    const int lane = tid & 31;
    const int gq = lane >> 2;
    const int tg = lane & 3;

    const int m0 = (wid & 3) * 32;
    const int n0 = (wid >> 2) * 64;

    float4 aTmp[4], bTmp[4];

    float acc[2][8][4];
    #pragma unroll
    for (int i = 0; i < 2; ++i)
        #pragma unroll
        for (int j = 0; j < 8; ++j)
            #pragma unroll
            for (int t = 0; t < 4; ++t) acc[i][j][t] = 0.f;

    const int nkt = K >> 5;

    #pragma unroll
    for (int l = 0; l < 4; ++l) {
        int v = tid + l * 256;
        aTmp[l] = *reinterpret_cast<const float4*>(A + (size_t)(bm + (v >> 3)) * K + ((v & 7) << 2));
        bTmp[l] = *reinterpret_cast<const float4*>(B + (size_t)(v >> 5) * N + bn + ((v & 31) << 2));
    }

    for (int kt = 0; kt < nkt; ++kt) {
        __syncthreads();
        #pragma unroll
        for (int l = 0; l < 4; ++l) {
            int v = tid + l * 256;
            float* ap = &As[(v >> 3) * LDA + ((v & 7) << 2)];
            ap[0] = f2tf32(aTmp[l].x); ap[1] = f2tf32(aTmp[l].y);
            ap[2] = f2tf32(aTmp[l].z); ap[3] = f2tf32(aTmp[l].w);
            float* bp = &Bs[(v >> 5) * LDB + ((v & 31) << 2)];
            bp[0] = f2tf32(bTmp[l].x); bp[1] = f2tf32(bTmp[l].y);
            bp[2] = f2tf32(bTmp[l].z); bp[3] = f2tf32(bTmp[l].w);
        }
        __syncthreads();

        if (kt + 1 < nkt) {
            const int koff = (kt + 1) << 5;
            #pragma unroll
            for (int l = 0; l < 4; ++l) {
                int v = tid + l * 256;
                aTmp[l] = *reinterpret_cast<const float4*>(A + (size_t)(bm + (v >> 3)) * K + koff + ((v & 7) << 2));
                bTmp[l] = *reinterpret_cast<const float4*>(B + (size_t)(koff + (v >> 5)) * N + bn + ((v & 31) << 2));
            }
        }

        #pragma unroll
        for (int kk = 0; kk < 4; ++kk) {
            const int k = kk << 3;
            uint32_t afr[2][4], bfr[8][2];
            #pragma unroll
            for (int i = 0; i < 2; ++i) {
                int r = m0 + i * 16 + gq;
                int c = k + tg;
                afr[i][0] = __float_as_uint(As[r * LDA + c]);
                afr[i][1] = __float_as_uint(As[(r + 8) * LDA + c]);
                afr[i][2] = __float_as_uint(As[r * LDA + c + 4]);
                afr[i][3] = __float_as_uint(As[(r + 8) * LDA + c + 4]);
            }
            #pragma unroll
            for (int j = 0; j < 8; ++j) {
                int col = n0 + j * 8 + gq;
                int row = k + tg;
                bfr[j][0] = __float_as_uint(Bs[row * LDB + col]);
                bfr[j][1] = __float_as_uint(Bs[(row + 4) * LDB + col]);
            }
            #pragma unroll
            for (int i = 0; i < 2; ++i)
                #pragma unroll
                for (int j = 0; j < 8; ++j)
                    mma_tf32(acc[i][j], afr[i], bfr[j]);
        }
    }

    #pragma unroll
    for (int i = 0; i < 2; ++i) {
        #pragma unroll
        for (int half = 0; half < 2; ++half) {
            int m = bm + m0 + i * 16 + gq + half * 8;
            #pragma unroll
            for (int j = 0; j < 8; ++j) {
                int n = bn + n0 + j * 8 + 2 * tg;
                float c0 = acc[i][j][half * 2 + 0] + bias[n];
                float c1 = acc[i][j][half * 2 + 1] + bias[n + 1];
                if (EPI == 1) { c0 = gelu_f(c0); c1 = gelu_f(c1); }
                if (EPI == 2) {
                    const float2 r2 = *reinterpret_cast<const float2*>(res + (size_t)m * N + n);
                    c0 += r2.x; c1 += r2.y;
                }
                float2 o2; o2.x = c0; o2.y = c1;
                *reinterpret_cast<float2*>(C + (size_t)m * N + n) = o2;
            }
        }
    }
}

// -------------------- Flash attention (causal, tf32 tensor cores) --------------------
// q-tile 128, kv-tile 64, 8 warps; warp w owns q-rows [w*16, w*16+16).
// grid: (SEQ/128, H, B), 256 threads.
#define PQ 68     // Qs, Ks, Ss pitch
#define PV 72     // Vs pitch (makes PV b-frag a bank permutation)

__global__ void __launch_bounds__(256, 1) flash_attn_k(
    const float* __restrict__ qkv, float* __restrict__ ctx)
{
    extern __shared__ float sm[];
    float* Qs = sm;                    // 128 x PQ
    float* Ks = Qs + 128 * PQ;         // 64 x PQ
    float* Vs = Ks + 64 * PQ;          // 64 x PV
    float* Ss = Vs + 64 * PV;          // 128 x PQ

    const int qt  = blockIdx.x;
    const int h   = blockIdx.y;
    const int b   = blockIdx.z;
    const int tid = threadIdx.x;
    const int wid = tid >> 5;
    const int lane = tid & 31;
    const int gq = lane >> 2;
    const int tg = lane & 3;
    const int wbase = wid * 16;
    const float scale = 0.03125f;      // 1/sqrt(1024)

    const size_t base = (size_t)b * SEQ * (3 * D_MODEL);
    const float* qp = qkv + base + h * HDIM;
    const float* kp = qkv + base + D_MODEL + h * HDIM;
    const float* vp = qkv + base + 2 * D_MODEL + h * HDIM;
    const int qbase = qt * 128;

    // load Q tile (scaled + tf32): 128x64, 8 float4/thread
    #pragma unroll
    for (int l = 0; l < 8; ++l) {
        int v = tid + l * 256;
        int r = v >> 4, c4 = (v & 15) * 4;
        float4 q4 = *reinterpret_cast<const float4*>(qp + (size_t)(qbase + r) * (3 * D_MODEL) + c4);
        float* dst = &Qs[r * PQ + c4];
        dst[0] = f2tf32(q4.x * scale); dst[1] = f2tf32(q4.y * scale);
        dst[2] = f2tf32(q4.z * scale); dst[3] = f2tf32(q4.w * scale);
    }

    float o[8][4];
    #pragma unroll
    for (int j = 0; j < 8; ++j)
        #pragma unroll
        for (int t = 0; t < 4; ++t) o[j][t] = 0.f;
    float m0r = -INFINITY, m1r = -INFINITY;
    float l0r = 0.f, l1r = 0.f;

    const int njt = 2 * qt + 2;

    for (int jt = 0; jt < njt; ++jt) {
        const int jbase = jt * 64;
        __syncthreads();
        // load K,V tiles (tf32): 64x64 each, 4 float4/thread each
        #pragma unroll
        for (int l = 0; l < 4; ++l) {
            int v = tid + l * 256;
            int r = v >> 4, c4 = (v & 15) * 4;
            float4 k4 = *reinterpret_cast<const float4*>(kp + (size_t)(jbase + r) * (3 * D_MODEL) + c4);
            float4 v4 = *reinterpret_cast<const float4*>(vp + (size_t)(jbase + r) * (3 * D_MODEL) + c4);
            float* kd = &Ks[r * PQ + c4];
            kd[0] = f2tf32(k4.x); kd[1] = f2tf32(k4.y);
            kd[2] = f2tf32(k4.z); kd[3] = f2tf32(k4.w);
            float* vd = &Vs[r * PV + c4];
            vd[0] = f2tf32(v4.x); vd[1] = f2tf32(v4.y);
            vd[2] = f2tf32(v4.z); vd[3] = f2tf32(v4.w);
        }
        __syncthreads();

        // S = Q @ K^T : warp tile 16 x 64
        float s[8][4];
        #pragma unroll
        for (int j = 0; j < 8; ++j)
            #pragma unroll
            for (int t = 0; t < 4; ++t) s[j][t] = 0.f;

        #pragma unroll
        for (int kk = 0; kk < 8; ++kk) {
            const int k = kk << 3;
            uint32_t afr[4];
            const int r = wbase + gq;
            const int c = k + tg;
            afr[0] = __float_as_uint(Qs[r * PQ + c]);
            afr[1] = __float_as_uint(Qs[(r + 8) * PQ + c]);
            afr[2] = __float_as_uint(Qs[r * PQ + c + 4]);
            afr[3] = __float_as_uint(Qs[(r + 8) * PQ + c + 4]);
            #pragma unroll
            for (int j = 0; j < 8; ++j) {
                uint32_t bfr[2];
                bfr[0] = __float_as_uint(Ks[(j * 8 + gq) * PQ + c]);
                bfr[1] = __float_as_uint(Ks[(j * 8 + gq) * PQ + c + 4]);
                mma_tf32(s[j], afr, bfr);
            }
        }

        // causal mask (only on the top two diagonal tiles)
        if (jt >= 2 * qt) {
            const int grow0 = qbase + wbase + gq;
            #pragma unroll
            for (int j = 0; j < 8; ++j) {
                int gc = jbase + j * 8 + 2 * tg;
                if (gc     > grow0)     s[j][0] = -1e30f;
                if (gc + 1 > grow0)     s[j][1] = -1e30f;
                if (gc     > grow0 + 8) s[j][2] = -1e30f;
                if (gc + 1 > grow0 + 8) s[j][3] = -1e30f;
            }
        }

        // online softmax in registers (row r0 = wbase+gq, r1 = +8)
        float tm0 = -INFINITY, tm1 = -INFINITY;
        #pragma unroll
        for (int j = 0; j < 8; ++j) {
            tm0 = fmaxf(tm0, fmaxf(s[j][0], s[j][1]));
            tm1 = fmaxf(tm1, fmaxf(s[j][2], s[j][3]));
        }
        tm0 = fmaxf(tm0, __shfl_xor_sync(0xffffffffu, tm0, 1));
        tm0 = fmaxf(tm0, __shfl_xor_sync(0xffffffffu, tm0, 2));
        tm1 = fmaxf(tm1, __shfl_xor_sync(0xffffffffu, tm1, 1));
        tm1 = fmaxf(tm1, __shfl_xor_sync(0xffffffffu, tm1, 2));

        float mn0 = fmaxf(m0r, tm0), mn1 = fmaxf(m1r, tm1);
        float cf0 = __expf(m0r - mn0), cf1 = __expf(m1r - mn1);
        m0r = mn0; m1r = mn1;

        float sum0 = 0.f, sum1 = 0.f;
        #pragma unroll
        for (int j = 0; j < 8; ++j) {
            float p0 = __expf(s[j][0] - mn0);
            float p1 = __expf(s[j][1] - mn0);
            float p2 = __expf(s[j][2] - mn1);
            float p3 = __expf(s[j][3] - mn1);
            sum0 += p0 + p1; sum1 += p2 + p3;
            s[j][0] = f2tf32(p0); s[j][1] = f2tf32(p1);
            s[j][2] = f2tf32(p2); s[j][3] = f2tf32(p3);
        }
        sum0 += __shfl_xor_sync(0xffffffffu, sum0, 1);
        sum0 += __shfl_xor_sync(0xffffffffu, sum0, 2);
        sum1 += __shfl_xor_sync(0xffffffffu, sum1, 1);
        sum1 += __shfl_xor_sync(0xffffffffu, sum1, 2);
        l0r = l0r * cf0 + sum0;
        l1r = l1r * cf1 + sum1;

        // rescale O
        #pragma unroll
        for (int j = 0; j < 8; ++j) {
            o[j][0] *= cf0; o[j][1] *= cf0;
            o[j][2] *= cf1; o[j][3] *= cf1;
        }

        // write P to Ss (per-warp rows only)
        {
            const int r0 = wbase + gq, r1 = r0 + 8;
            #pragma unroll
            for (int j = 0; j < 8; ++j) {
                const int c = j * 8 + 2 * tg;
                *reinterpret_cast<float2*>(&Ss[r0 * PQ + c]) = make_float2(s[j][0], s[j][1]);
                *reinterpret_cast<float2*>(&Ss[r1 * PQ + c]) = make_float2(s[j][2], s[j][3]);
            }
        }
        __syncwarp();

        // O += P @ V : k over 64 kv
        #pragma unroll
        for (int kk = 0; kk < 8; ++kk) {
            const int k = kk << 3;
            uint32_t afr[4];
            const int r = wbase + gq;
            const int c = k + tg;
            afr[0] = __float_as_uint(Ss[r * PQ + c]);
            afr[1] = __float_as_uint(Ss[(r + 8) * PQ + c]);
            afr[2] = __float_as_uint(Ss[r * PQ + c + 4]);
            afr[3] = __float_as_uint(Ss[(r + 8) * PQ + c + 4]);
            #pragma unroll
            for (int j = 0; j < 8; ++j) {
                uint32_t bfr[2];
                bfr[0] = __float_as_uint(Vs[(k + tg) * PV + j * 8 + gq]);
                bfr[1] = __float_as_uint(Vs[(k + tg + 4) * PV + j * 8 + gq]);
                mma_tf32(o[j], afr, bfr);
            }
        }
    }

    // epilogue
    const float inv0 = 1.f / l0r, inv1 = 1.f / l1r;
    const int grow0 = qbase + wbase + gq;
    const size_t obase = ((size_t)b * SEQ + grow0) * D_MODEL + h * HDIM;
    #pragma unroll
    for (int j = 0; j < 8; ++j) {
        const int c = j * 8 + 2 * tg;
        *reinterpret_cast<float2*>(ctx + obase + c) =
            make_float2(o[j][0] * inv0, o[j][1] * inv0);
        *reinterpret_cast<float2*>(ctx + obase + (size_t)8 * D_MODEL + c) =
            make_float2(o[j][2] * inv1, o[j][3] * inv1);
    }
}

// -------------------- launch --------------------
extern "C" void kernel_launch(void* const* d_in, const int* in_sizes, int n_in,
                              void* d_out, int out_size)
{
    const float* x     = (const float*)d_in[0];
    const float* w_qkv = (const float*)d_in[1];
    const float* b_qkv = (const float*)d_in[2];
    const float* w_o   = (const float*)d_in[3];
    const float* b_o   = (const float*)d_in[4];
    const float* g1    = (const float*)d_in[5];
    const float* be1   = (const float*)d_in[6];
    const float* g2    = (const float*)d_in[7];
    const float* be2   = (const float*)d_in[8];
    const float* w1    = (const float*)d_in[9];
    const float* b1    = (const float*)d_in[10];
    const float* w2    = (const float*)d_in[11];
    const float* b2    = (const float*)d_in[12];
    float* out = (float*)d_out;

    float *p_nx, *p_qkv, *p_ctx, *p_x1, *p_h;
    cudaGetSymbolAddress((void**)&p_nx,  g_nx);
    cudaGetSymbolAddress((void**)&p_qkv, g_qkv);
    cudaGetSymbolAddress((void**)&p_ctx, g_ctx);
    cudaGetSymbolAddress((void**)&p_x1,  g_x1);
    cudaGetSymbolAddress((void**)&p_h,   g_h);

    static const int FLASH_SMEM =
        (128 * PQ + 64 * PQ + 64 * PV + 128 * PQ) * (int)sizeof(float);  // ~103 KB
    cudaFuncSetAttribute(flash_attn_k, cudaFuncAttributeMaxDynamicSharedMemorySize, FLASH_SMEM);

    // 1) nx = LN1(x)
    ln_kernel<<<NROWS, 256>>>(x, g1, be1, p_nx);

    // 2) qkv = nx @ w_qkv + b_qkv     [4096, 3072]
    tgemm_k<0><<<dim3(3 * D_MODEL / 128, NROWS / 128), 256>>>(
        p_nx, w_qkv, b_qkv, nullptr, p_qkv, NROWS, 3 * D_MODEL, D_MODEL);

    // 3) ctx = causal attention(q,k,v)
    flash_attn_k<<<dim3(SEQ / 128, NHEAD, BATCH), 256, FLASH_SMEM>>>(p_qkv, p_ctx);

    // 4) x1 = x + ctx @ w_o + b_o
    tgemm_k<2><<<dim3(D_MODEL / 128, NROWS / 128), 256>>>(
        p_ctx, w_o, b_o, x, p_x1, NROWS, D_MODEL, D_MODEL);

    // 5) nx = LN2(x1)
    ln_kernel<<<NROWS, 256>>>(p_x1, g2, be2, p_nx);

    // 6) h = gelu(nx @ w1 + b1)       [4096, 4096]
    tgemm_k<1><<<dim3(D_MID / 128, NROWS / 128), 256>>>(
        p_nx, w1, b1, nullptr, p_h, NROWS, D_MID, D_MODEL);

    // 7) out = x1 + h @ w2 + b2       [4096, 1024]
    tgemm_k<2><<<dim3(D_MODEL / 128, NROWS / 128), 256>>>(
        p_h, w2, b2, p_x1, out, NROWS, D_MODEL, D_MID);
}

// round 7
// speedup vs baseline: 3.5532x; 1.1574x over previous
#include <cuda_runtime.h>
#include <cuda_bf16.h>
#include <math.h>
#include <stdint.h>

#define D_MODEL 1024
#define D_MID   4096
#define NHEAD   16
#define HDIM    64
#define SEQ     2048
#define BATCH   2
#define NROWS   (BATCH * SEQ)      // 4096
#define LN_EPS  1e-5f

// -------------------- scratch (device globals, no allocation) --------------------
__device__ float g_nx  [NROWS * D_MODEL];
__device__ float g_qkv [NROWS * 3 * D_MODEL];
__device__ float g_ctx [NROWS * D_MODEL];
__device__ float g_x1  [NROWS * D_MODEL];
__device__ float g_h   [NROWS * D_MID];
// tf32-converted weights
__device__ float g_wqkv[D_MODEL * 3 * D_MODEL];
__device__ float g_wo  [D_MODEL * D_MODEL];
__device__ float g_w1  [D_MODEL * D_MID];
__device__ float g_w2  [D_MID * D_MODEL];

// -------------------- helpers --------------------
__device__ __forceinline__ float f2tf32(float f) {
    uint32_t r;
    asm("cvt.rna.tf32.f32 %0, %1;" : "=r"(r) : "f"(f));
    return __uint_as_float(r);
}

__device__ __forceinline__ void mma_tf32(
    float c[4], const uint32_t a[4], const uint32_t b[2])
{
    asm volatile(
        "mma.sync.aligned.m16n8k8.row.col.f32.tf32.tf32.f32 "
        "{%0,%1,%2,%3}, {%4,%5,%6,%7}, {%8,%9}, {%0,%1,%2,%3};"
        : "+f"(c[0]), "+f"(c[1]), "+f"(c[2]), "+f"(c[3])
        : "r"(a[0]), "r"(a[1]), "r"(a[2]), "r"(a[3]),
          "r"(b[0]), "r"(b[1]));
}

__device__ __forceinline__ void cp_async16(void* sptr, const void* gptr) {
    uint32_t s = (uint32_t)__cvta_generic_to_shared(sptr);
    asm volatile("cp.async.cg.shared.global [%0], [%1], 16;" :: "r"(s), "l"(gptr));
}
#define CP_COMMIT() asm volatile("cp.async.commit_group;")
#define CP_WAIT(n)  asm volatile("cp.async.wait_group %0;" :: "n"(n))

__device__ __forceinline__ float gelu_f(float x) {
    float x3 = x * x * x;
    return 0.5f * x * (1.f + tanhf(0.7978845608028654f * (x + 0.044715f * x3)));
}

// -------------------- weight tf32 conversion --------------------
__global__ void __launch_bounds__(256) cvt_tf32_k(
    const float* __restrict__ in, float* __restrict__ o, int n4)
{
    int i = blockIdx.x * blockDim.x + threadIdx.x;
    int stride = gridDim.x * blockDim.x;
    for (; i < n4; i += stride) {
        float4 v = reinterpret_cast<const float4*>(in)[i];
        v.x = f2tf32(v.x); v.y = f2tf32(v.y);
        v.z = f2tf32(v.z); v.w = f2tf32(v.w);
        reinterpret_cast<float4*>(o)[i] = v;
    }
}

// -------------------- LayerNorm (tf32-rounded output) --------------------
__global__ void __launch_bounds__(256) ln_kernel(
    const float* __restrict__ x, const float* __restrict__ g,
    const float* __restrict__ be, float* __restrict__ out)
{
    int row = blockIdx.x;
    int tid = threadIdx.x;
    const float4* xr = reinterpret_cast<const float4*>(x + (size_t)row * D_MODEL);
    float4 v = xr[tid];
    float s  = v.x + v.y + v.z + v.w;
    float ss = v.x*v.x + v.y*v.y + v.z*v.z + v.w*v.w;

    __shared__ float shs[8], shss[8];
    #pragma unroll
    for (int o = 16; o > 0; o >>= 1) {
        s  += __shfl_down_sync(0xffffffffu, s,  o);
        ss += __shfl_down_sync(0xffffffffu, ss, o);
    }
    int w = tid >> 5, lane = tid & 31;
    if (lane == 0) { shs[w] = s; shss[w] = ss; }
    __syncthreads();
    if (w == 0) {
        s  = (lane < 8) ? shs[lane]  : 0.f;
        ss = (lane < 8) ? shss[lane] : 0.f;
        #pragma unroll
        for (int o = 4; o > 0; o >>= 1) {
            s  += __shfl_down_sync(0xffffffffu, s,  o);
            ss += __shfl_down_sync(0xffffffffu, ss, o);
        }
        if (lane == 0) { shs[0] = s; shss[0] = ss; }
    }
    __syncthreads();
    float mu  = shs[0] * (1.f / D_MODEL);
    float var = shss[0] * (1.f / D_MODEL) - mu * mu;
    float rstd = rsqrtf(var + LN_EPS);

    float4 gv = reinterpret_cast<const float4*>(g)[tid];
    float4 bv = reinterpret_cast<const float4*>(be)[tid];
    float4 o4;
    o4.x = f2tf32((v.x - mu) * rstd * gv.x + bv.x);
    o4.y = f2tf32((v.y - mu) * rstd * gv.y + bv.y);
    o4.z = f2tf32((v.z - mu) * rstd * gv.z + bv.z);
    o4.w = f2tf32((v.w - mu) * rstd * gv.w + bv.w);
    reinterpret_cast<float4*>(out + (size_t)row * D_MODEL)[tid] = o4;
}

// -------------------- TF32 tensor-core GEMM, 4-stage cp.async --------------------
// C[M,N] = A[M,K] @ B[K,N] + bias (+epilogue)
// Inputs must already be tf32-rounded. EPI: 0 bias, 1 bias+GELU, 2 bias+residual.
// ROUND: round output to tf32.
#define LDA 36
#define LDB 136
#define STAGES 4
#define SSZ (128 * LDA + 32 * LDB)     // floats per stage

template<int EPI, int ROUND>
__global__ void __launch_bounds__(256) tgemm_k(
    const float* __restrict__ A, const float* __restrict__ B,
    const float* __restrict__ bias, const float* __restrict__ res,
    float* __restrict__ C, int M, int N, int K)
{
    extern __shared__ float smp[];

    const int bm = blockIdx.y * 128;
    const int bn = blockIdx.x * 128;
    const int tid  = threadIdx.x;
    const int wid  = tid >> 5;
    const int lane = tid & 31;
    const int gq = lane >> 2;
    const int tg = lane & 3;

    const int m0 = (wid & 3) * 32;
    const int n0 = (wid >> 2) * 64;

    const int nkt = K >> 5;

    auto issue = [&](int stage, int kt) {
        float* As = smp + stage * SSZ;
        float* Bs = As + 128 * LDA;
        const int ko = kt << 5;
        #pragma unroll
        for (int l = 0; l < 4; ++l) {
            int v = tid + l * 256;
            cp_async16(&As[(v >> 3) * LDA + ((v & 7) << 2)],
                       A + (size_t)(bm + (v >> 3)) * K + ko + ((v & 7) << 2));
            cp_async16(&Bs[(v >> 5) * LDB + ((v & 31) << 2)],
                       B + (size_t)(ko + (v >> 5)) * N + bn + ((v & 31) << 2));
        }
    };

    // prologue: stages 0..2
    #pragma unroll
    for (int s = 0; s < STAGES - 1; ++s) { issue(s, s); CP_COMMIT(); }

    float acc[2][8][4];
    #pragma unroll
    for (int i = 0; i < 2; ++i)
        #pragma unroll
        for (int j = 0; j < 8; ++j)
            #pragma unroll
            for (int t = 0; t < 4; ++t) acc[i][j][t] = 0.f;

    for (int kt = 0; kt < nkt; ++kt) {
        CP_WAIT(2);
        __syncthreads();
        if (kt + STAGES - 1 < nkt) issue((kt + STAGES - 1) & 3, kt + STAGES - 1);
        CP_COMMIT();

        const float* As = smp + (kt & 3) * SSZ;
        const float* Bs = As + 128 * LDA;

        #pragma unroll
        for (int kk = 0; kk < 4; ++kk) {
            const int k = kk << 3;
            uint32_t afr[2][4], bfr[8][2];
            #pragma unroll
            for (int i = 0; i < 2; ++i) {
                int r = m0 + i * 16 + gq;
                int c = k + tg;
                afr[i][0] = __float_as_uint(As[r * LDA + c]);
                afr[i][1] = __float_as_uint(As[(r + 8) * LDA + c]);
                afr[i][2] = __float_as_uint(As[r * LDA + c + 4]);
                afr[i][3] = __float_as_uint(As[(r + 8) * LDA + c + 4]);
            }
            #pragma unroll
            for (int j = 0; j < 8; ++j) {
                int col = n0 + j * 8 + gq;
                int row = k + tg;
                bfr[j][0] = __float_as_uint(Bs[row * LDB + col]);
                bfr[j][1] = __float_as_uint(Bs[(row + 4) * LDB + col]);
            }
            #pragma unroll
            for (int i = 0; i < 2; ++i)
                #pragma unroll
                for (int j = 0; j < 8; ++j)
                    mma_tf32(acc[i][j], afr[i], bfr[j]);
        }
    }

    #pragma unroll
    for (int i = 0; i < 2; ++i) {
        #pragma unroll
        for (int half = 0; half < 2; ++half) {
            int m = bm + m0 + i * 16 + gq + half * 8;
            #pragma unroll
            for (int j = 0; j < 8; ++j) {
                int n = bn + n0 + j * 8 + 2 * tg;
                float c0 = acc[i][j][half * 2 + 0] + bias[n];
                float c1 = acc[i][j][half * 2 + 1] + bias[n + 1];
                if (EPI == 1) { c0 = gelu_f(c0); c1 = gelu_f(c1); }
                if (EPI == 2) {
                    const float2 r2 = *reinterpret_cast<const float2*>(res + (size_t)m * N + n);
                    c0 += r2.x; c1 += r2.y;
                }
                if (ROUND) { c0 = f2tf32(c0); c1 = f2tf32(c1); }
                float2 o2; o2.x = c0; o2.y = c1;
                *reinterpret_cast<float2*>(C + (size_t)m * N + n) = o2;
            }
        }
    }
}

// -------------------- Flash attention (causal, tf32, cp.async double buffer) ---
// q-tile 128, kv-tile 64, 8 warps; warp w owns q-rows [w*16, w*16+16).
// qkv must be tf32-rounded. Scale folded into S (2^-5 exact).
#define PQ 68
#define PV 72
#define KVSZ (64 * PQ + 64 * PV)

__global__ void __launch_bounds__(256, 1) flash_attn_k(
    const float* __restrict__ qkv, float* __restrict__ ctx)
{
    extern __shared__ float sm[];
    float* Qs  = sm;                       // 128 x PQ
    float* KV0 = Qs + 128 * PQ;            // 2 stages of (K 64xPQ, V 64xPV)
    float* Ss  = KV0 + 2 * KVSZ;           // 128 x PQ

    const int qt  = blockIdx.x;
    const int h   = blockIdx.y;
    const int b   = blockIdx.z;
    const int tid = threadIdx.x;
    const int wid = tid >> 5;
    const int lane = tid & 31;
    const int gq = lane >> 2;
    const int tg = lane & 3;
    const int wbase = wid * 16;
    const float scale = 0.03125f;          // 1/sqrt(1024) = 2^-5, exact

    const size_t base = (size_t)b * SEQ * (3 * D_MODEL);
    const float* qp = qkv + base + h * HDIM;
    const float* kp = qkv + base + D_MODEL + h * HDIM;
    const float* vp = qkv + base + 2 * D_MODEL + h * HDIM;
    const int qbase = qt * 128;
    const int njt = 2 * qt + 2;

    auto issue_kv = [&](int jt, int buf) {
        float* Ks = KV0 + buf * KVSZ;
        float* Vs = Ks + 64 * PQ;
        const int jb = jt * 64;
        #pragma unroll
        for (int l = 0; l < 4; ++l) {
            int v = tid + l * 256;
            int r = v >> 4, c4 = (v & 15) << 2;
            cp_async16(&Ks[r * PQ + c4], kp + (size_t)(jb + r) * (3 * D_MODEL) + c4);
            cp_async16(&Vs[r * PV + c4], vp + (size_t)(jb + r) * (3 * D_MODEL) + c4);
        }
    };

    // prologue: Q + KV(0) in group 0
    #pragma unroll
    for (int l = 0; l < 8; ++l) {
        int v = tid + l * 256;
        int r = v >> 4, c4 = (v & 15) << 2;
        cp_async16(&Qs[r * PQ + c4], qp + (size_t)(qbase + r) * (3 * D_MODEL) + c4);
    }
    issue_kv(0, 0);
    CP_COMMIT();

    float o[8][4];
    #pragma unroll
    for (int j = 0; j < 8; ++j)
        #pragma unroll
        for (int t = 0; t < 4; ++t) o[j][t] = 0.f;
    float m0r = -INFINITY, m1r = -INFINITY;
    float l0r = 0.f, l1r = 0.f;

    for (int jt = 0; jt < njt; ++jt) {
        if (jt + 1 < njt) issue_kv(jt + 1, (jt + 1) & 1);
        CP_COMMIT();
        CP_WAIT(1);
        __syncthreads();

        const float* Ks = KV0 + (jt & 1) * KVSZ;
        const float* Vs = Ks + 64 * PQ;

        // S = Q @ K^T : warp tile 16 x 64
        float s[8][4];
        #pragma unroll
        for (int j = 0; j < 8; ++j)
            #pragma unroll
            for (int t = 0; t < 4; ++t) s[j][t] = 0.f;

        #pragma unroll
        for (int kk = 0; kk < 8; ++kk) {
            const int k = kk << 3;
            uint32_t afr[4];
            const int r = wbase + gq;
            const int c = k + tg;
            afr[0] = __float_as_uint(Qs[r * PQ + c]);
            afr[1] = __float_as_uint(Qs[(r + 8) * PQ + c]);
            afr[2] = __float_as_uint(Qs[r * PQ + c + 4]);
            afr[3] = __float_as_uint(Qs[(r + 8) * PQ + c + 4]);
            #pragma unroll
            for (int j = 0; j < 8; ++j) {
                uint32_t bfr[2];
                bfr[0] = __float_as_uint(Ks[(j * 8 + gq) * PQ + c]);
                bfr[1] = __float_as_uint(Ks[(j * 8 + gq) * PQ + c + 4]);
                mma_tf32(s[j], afr, bfr);
            }
        }

        // apply score scale
        #pragma unroll
        for (int j = 0; j < 8; ++j) {
            s[j][0] *= scale; s[j][1] *= scale;
            s[j][2] *= scale; s[j][3] *= scale;
        }

        // causal mask (top two diagonal tiles only)
        if (jt >= 2 * qt) {
            const int grow0 = qbase + wbase + gq;
            const int jbase = jt * 64;
            #pragma unroll
            for (int j = 0; j < 8; ++j) {
                int gc = jbase + j * 8 + 2 * tg;
                if (gc     > grow0)     s[j][0] = -1e30f;
                if (gc + 1 > grow0)     s[j][1] = -1e30f;
                if (gc     > grow0 + 8) s[j][2] = -1e30f;
                if (gc + 1 > grow0 + 8) s[j][3] = -1e30f;
            }
        }

        // online softmax in registers
        float tm0 = -INFINITY, tm1 = -INFINITY;
        #pragma unroll
        for (int j = 0; j < 8; ++j) {
            tm0 = fmaxf(tm0, fmaxf(s[j][0], s[j][1]));
            tm1 = fmaxf(tm1, fmaxf(s[j][2], s[j][3]));
        }
        tm0 = fmaxf(tm0, __shfl_xor_sync(0xffffffffu, tm0, 1));
        tm0 = fmaxf(tm0, __shfl_xor_sync(0xffffffffu, tm0, 2));
        tm1 = fmaxf(tm1, __shfl_xor_sync(0xffffffffu, tm1, 1));
        tm1 = fmaxf(tm1, __shfl_xor_sync(0xffffffffu, tm1, 2));

        float mn0 = fmaxf(m0r, tm0), mn1 = fmaxf(m1r, tm1);
        float cf0 = __expf(m0r - mn0), cf1 = __expf(m1r - mn1);
        m0r = mn0; m1r = mn1;

        float sum0 = 0.f, sum1 = 0.f;
        #pragma unroll
        for (int j = 0; j < 8; ++j) {
            float p0 = __expf(s[j][0] - mn0);
            float p1 = __expf(s[j][1] - mn0);
            float p2 = __expf(s[j][2] - mn1);
            float p3 = __expf(s[j][3] - mn1);
            sum0 += p0 + p1; sum1 += p2 + p3;
            s[j][0] = f2tf32(p0); s[j][1] = f2tf32(p1);
            s[j][2] = f2tf32(p2); s[j][3] = f2tf32(p3);
        }
        sum0 += __shfl_xor_sync(0xffffffffu, sum0, 1);
        sum0 += __shfl_xor_sync(0xffffffffu, sum0, 2);
        sum1 += __shfl_xor_sync(0xffffffffu, sum1, 1);
        sum1 += __shfl_xor_sync(0xffffffffu, sum1, 2);
        l0r = l0r * cf0 + sum0;
        l1r = l1r * cf1 + sum1;

        #pragma unroll
        for (int j = 0; j < 8; ++j) {
            o[j][0] *= cf0; o[j][1] *= cf0;
            o[j][2] *= cf1; o[j][3] *= cf1;
        }

        // write P to Ss (per-warp rows)
        {
            const int r0 = wbase + gq, r1 = r0 + 8;
            #pragma unroll
            for (int j = 0; j < 8; ++j) {
                const int c = j * 8 + 2 * tg;
                *reinterpret_cast<float2*>(&Ss[r0 * PQ + c]) = make_float2(s[j][0], s[j][1]);
                *reinterpret_cast<float2*>(&Ss[r1 * PQ + c]) = make_float2(s[j][2], s[j][3]);
            }
        }
        __syncwarp();

        // O += P @ V
        #pragma unroll
        for (int kk = 0; kk < 8; ++kk) {
            const int k = kk << 3;
            uint32_t afr[4];
            const int r = wbase + gq;
            const int c = k + tg;
            afr[0] = __float_as_uint(Ss[r * PQ + c]);
            afr[1] = __float_as_uint(Ss[(r + 8) * PQ + c]);
            afr[2] = __float_as_uint(Ss[r * PQ + c + 4]);
            afr[3] = __float_as_uint(Ss[(r + 8) * PQ + c + 4]);
            #pragma unroll
            for (int j = 0; j < 8; ++j) {
                uint32_t bfr[2];
                bfr[0] = __float_as_uint(Vs[(k + tg) * PV + j * 8 + gq]);
                bfr[1] = __float_as_uint(Vs[(k + tg + 4) * PV + j * 8 + gq]);
                mma_tf32(o[j], afr, bfr);
            }
        }
        __syncthreads();
    }

    // epilogue (tf32-rounded — feeds O-proj GEMM)
    const float inv0 = 1.f / l0r, inv1 = 1.f / l1r;
    const int grow0 = qbase + wbase + gq;
    const size_t obase = ((size_t)b * SEQ + grow0) * D_MODEL + h * HDIM;
    #pragma unroll
    for (int j = 0; j < 8; ++j) {
        const int c = j * 8 + 2 * tg;
        *reinterpret_cast<float2*>(ctx + obase + c) =
            make_float2(f2tf32(o[j][0] * inv0), f2tf32(o[j][1] * inv0));
        *reinterpret_cast<float2*>(ctx + obase + (size_t)8 * D_MODEL + c) =
            make_float2(f2tf32(o[j][2] * inv1), f2tf32(o[j][3] * inv1));
    }
}

// -------------------- launch --------------------
extern "C" void kernel_launch(void* const* d_in, const int* in_sizes, int n_in,
                              void* d_out, int out_size)
{
    const float* x     = (const float*)d_in[0];
    const float* w_qkv = (const float*)d_in[1];
    const float* b_qkv = (const float*)d_in[2];
    const float* w_o   = (const float*)d_in[3];
    const float* b_o   = (const float*)d_in[4];
    const float* g1    = (const float*)d_in[5];
    const float* be1   = (const float*)d_in[6];
    const float* g2    = (const float*)d_in[7];
    const float* be2   = (const float*)d_in[8];
    const float* w1    = (const float*)d_in[9];
    const float* b1    = (const float*)d_in[10];
    const float* w2    = (const float*)d_in[11];
    const float* b2    = (const float*)d_in[12];
    float* out = (float*)d_out;

    float *p_nx, *p_qkv, *p_ctx, *p_x1, *p_h;
    float *p_wqkv, *p_wo, *p_w1, *p_w2;
    cudaGetSymbolAddress((void**)&p_nx,   g_nx);
    cudaGetSymbolAddress((void**)&p_qkv,  g_qkv);
    cudaGetSymbolAddress((void**)&p_ctx,  g_ctx);
    cudaGetSymbolAddress((void**)&p_x1,   g_x1);
    cudaGetSymbolAddress((void**)&p_h,    g_h);
    cudaGetSymbolAddress((void**)&p_wqkv, g_wqkv);
    cudaGetSymbolAddress((void**)&p_wo,   g_wo);
    cudaGetSymbolAddress((void**)&p_w1,   g_w1);
    cudaGetSymbolAddress((void**)&p_w2,   g_w2);

    static const int GEMM_SMEM  = STAGES * SSZ * (int)sizeof(float);                 // ~143 KB
    static const int FLASH_SMEM = (128 * PQ + 2 * KVSZ + 128 * PQ) * (int)sizeof(float); // ~141 KB
    cudaFuncSetAttribute(tgemm_k<0,1>, cudaFuncAttributeMaxDynamicSharedMemorySize, GEMM_SMEM);
    cudaFuncSetAttribute(tgemm_k<1,1>, cudaFuncAttributeMaxDynamicSharedMemorySize, GEMM_SMEM);
    cudaFuncSetAttribute(tgemm_k<2,0>, cudaFuncAttributeMaxDynamicSharedMemorySize, GEMM_SMEM);
    cudaFuncSetAttribute(flash_attn_k, cudaFuncAttributeMaxDynamicSharedMemorySize, FLASH_SMEM);

    // 0) weights -> tf32
    cvt_tf32_k<<<1184, 256>>>(w_qkv, p_wqkv, D_MODEL * 3 * D_MODEL / 4);
    cvt_tf32_k<<<1184, 256>>>(w_o,   p_wo,   D_MODEL * D_MODEL / 4);
    cvt_tf32_k<<<1184, 256>>>(w1,    p_w1,   D_MODEL * D_MID / 4);
    cvt_tf32_k<<<1184, 256>>>(w2,    p_w2,   D_MID * D_MODEL / 4);

    // 1) nx = LN1(x)  (tf32-rounded)
    ln_kernel<<<NROWS, 256>>>(x, g1, be1, p_nx);

    // 2) qkv = nx @ w_qkv + b_qkv  (tf32-rounded)
    tgemm_k<0,1><<<dim3(3 * D_MODEL / 128, NROWS / 128), 256, GEMM_SMEM>>>(
        p_nx, p_wqkv, b_qkv, nullptr, p_qkv, NROWS, 3 * D_MODEL, D_MODEL);

    // 3) ctx = causal attention(q,k,v)  (tf32-rounded)
    flash_attn_k<<<dim3(SEQ / 128, NHEAD, BATCH), 256, FLASH_SMEM>>>(p_qkv, p_ctx);

    // 4) x1 = x + ctx @ w_o + b_o  (full fp32)
    tgemm_k<2,0><<<dim3(D_MODEL / 128, NROWS / 128), 256, GEMM_SMEM>>>(
        p_ctx, p_wo, b_o, x, p_x1, NROWS, D_MODEL, D_MODEL);

    // 5) nx = LN2(x1)  (tf32-rounded)
    ln_kernel<<<NROWS, 256>>>(p_x1, g2, be2, p_nx);

    // 6) h = gelu(nx @ w1 + b1)  (tf32-rounded)
    tgemm_k<1,1><<<dim3(D_MID / 128, NROWS / 128), 256, GEMM_SMEM>>>(
        p_nx, p_w1, b1, nullptr, p_h, NROWS, D_MID, D_MODEL);

    // 7) out = x1 + h @ w2 + b2  (full fp32)
    tgemm_k<2,0><<<dim3(D_MODEL / 128, NROWS / 128), 256, GEMM_SMEM>>>(
        p_h, p_w2, b2, p_x1, out, NROWS, D_MODEL, D_MID);
}